// round 2
// baseline (speedup 1.0000x reference)
#include <cuda_runtime.h>
#include <math.h>

#define NANCH 261888
#define TOPK 1000
#define IOU_T 0.7f
#define SCLAMP 4.1351665567423557f   // log(1000/16)

// ---------------- scratch (device globals; no allocation) ----------------
__device__ float g_t[33554432];            // conv3x3 output, reused per level (2*256*256*256)
__device__ float g_wT[589824];             // transposed conv weights [cin*9+k][cout]
__device__ float g_scores[2 * NANCH];
__device__ float4 g_boxes[2 * NANCH];
__device__ unsigned int g_hist[2][256];
__device__ unsigned long long g_pref[2];
__device__ int g_need[2];
__device__ int g_cnt[2];
__device__ unsigned long long g_selkey[2][1024];
__device__ float4 g_nbox[2 * TOPK];
__device__ unsigned int g_mask[2][TOPK][32];
__device__ unsigned int g_keep[2][32];

// ---------------- f32x2 packed helpers (sm_103a) ----------------
__device__ __forceinline__ void fma2(unsigned long long& acc, unsigned long long a,
                                     unsigned long long b) {
    asm("fma.rn.f32x2 %0, %1, %2, %0;" : "+l"(acc) : "l"(a), "l"(b));
}
__device__ __forceinline__ unsigned long long pack2(float x, float y) {
    unsigned long long r;
    asm("mov.b64 %0, {%1, %2};" : "=l"(r) : "f"(x), "f"(y));
    return r;
}
__device__ __forceinline__ void unpack2(float& lo, float& hi, unsigned long long v) {
    asm("mov.b64 {%0, %1}, %2;" : "=f"(lo), "=f"(hi) : "l"(v));
}

// ---------------- weight transpose: conv_w (Cout,Cin,3,3) -> [cin*9+k][cout] ----------------
__global__ void transpose_w_kernel(const float* __restrict__ w) {
    int i = blockIdx.x * blockDim.x + threadIdx.x;
    if (i < 589824) {
        int cout = i & 255;        // i = rk*256 + cout
        int rk = i >> 8;           // rk = cin*9 + k
        g_wT[i] = w[cout * 2304 + rk];
    }
}

// ---------------- state init (must run every launch: graph replays) ----------------
__global__ void init_state_kernel() {
    int t = threadIdx.x;
    if (t < 2) { g_pref[t] = 0ULL; g_need[t] = TOPK; g_cnt[t] = 0; }
    if (t < 256) { g_hist[0][t] = 0u; g_hist[1][t] = 0u; }
}

// ---------------- 3x3 conv + bias + relu (fp32, packed f32x2 FMA) ----------------
// block: 256 threads. tile = 8x8 pixels, all 256 output channels.
// thread: coutq = tid&31 -> couts coutq*8..+7 (as 4 f32x2 pairs); prow = tid>>5.
__global__ __launch_bounds__(256, 2)
void conv3x3_kernel(const float* __restrict__ x, const float* __restrict__ bias,
                    int H, int W) {
    const int tx0 = blockIdx.x * 8, ty0 = blockIdx.y * 8, b = blockIdx.z;
    const int tid = threadIdx.x;
    const int coutq = tid & 31;
    const int prow = tid >> 5;
    __shared__ float sx[4][10][10];
    __shared__ __align__(16) float sw[4 * 9 * 256];
    // acc2[p][px] = packed pair (cout = coutq*8+2p, coutq*8+2p+1) at pixel px
    unsigned long long acc2[4][8];
#pragma unroll
    for (int p = 0; p < 4; p++)
#pragma unroll
        for (int j = 0; j < 8; j++) acc2[p][j] = 0ULL;

    const size_t HW = (size_t)H * W;
    const float* xb = x + (size_t)b * 256 * HW;

    for (int c0 = 0; c0 < 256; c0 += 4) {
        __syncthreads();
        // input patch: 4 cins x 10x10 (zero-padded borders)
        for (int i = tid; i < 400; i += 256) {
            int ci = i / 100, p = i % 100, py = p / 10, px = p % 10;
            int gy = ty0 - 1 + py, gx = tx0 - 1 + px;
            float v = 0.f;
            if (gy >= 0 && gy < H && gx >= 0 && gx < W)
                v = xb[(size_t)(c0 + ci) * HW + (size_t)gy * W + gx];
            sx[ci][py][px] = v;
        }
        // weights: 4 cins x 9 x 256 couts, coalesced from pre-transposed g_wT
        const float* wsrc = g_wT + (size_t)c0 * 9 * 256;
        for (int i = tid; i < 9216; i += 256) sw[i] = wsrc[i];
        __syncthreads();

#pragma unroll
        for (int ci = 0; ci < 4; ci++) {
            float xr[3][10];
#pragma unroll
            for (int r = 0; r < 3; r++)
#pragma unroll
                for (int j = 0; j < 10; j++) xr[r][j] = sx[ci][prow + r][j];
#pragma unroll
            for (int k = 0; k < 9; k++) {
                const int ky = k / 3, kx = k % 3;
                const ulonglong2* wrow = (const ulonglong2*)(sw + (ci * 9 + k) * 256);
                ulonglong2 wA = wrow[coutq * 2];
                ulonglong2 wB = wrow[coutq * 2 + 1];
#pragma unroll
                for (int px = 0; px < 8; px++) {
                    float xv = xr[ky][px + kx];
                    unsigned long long xv2 = pack2(xv, xv);
                    fma2(acc2[0][px], xv2, wA.x);
                    fma2(acc2[1][px], xv2, wA.y);
                    fma2(acc2[2][px], xv2, wB.x);
                    fma2(acc2[3][px], xv2, wB.y);
                }
            }
        }
    }
    // epilogue: relu(acc + bias) -> g_t[b][cout][y][x], float4 stores
    const size_t ob = (size_t)b * 256 * HW;
    const int y = ty0 + prow;
#pragma unroll
    for (int p = 0; p < 4; p++) {
        int cout0 = coutq * 8 + 2 * p;
        float bv0 = bias[cout0], bv1 = bias[cout0 + 1];
        float o0[8], o1[8];
#pragma unroll
        for (int px = 0; px < 8; px++) {
            float lo, hi;
            unpack2(lo, hi, acc2[p][px]);
            lo += bv0; hi += bv1;
            o0[px] = lo > 0.f ? lo : 0.f;
            o1[px] = hi > 0.f ? hi : 0.f;
        }
        float4* d0 = (float4*)(g_t + ob + (size_t)cout0 * HW + (size_t)y * W + tx0);
        d0[0] = make_float4(o0[0], o0[1], o0[2], o0[3]);
        d0[1] = make_float4(o0[4], o0[5], o0[6], o0[7]);
        float4* d1 = (float4*)(g_t + ob + (size_t)(cout0 + 1) * HW + (size_t)y * W + tx0);
        d1[0] = make_float4(o1[0], o1[1], o1[2], o1[3]);
        d1[1] = make_float4(o1[4], o1[5], o1[6], o1[7]);
    }
}

// ---------------- 1x1 heads + sigmoid + decode + clip ----------------
__global__ __launch_bounds__(256)
void head_kernel(const float* __restrict__ objw, const float* __restrict__ objb,
                 const float* __restrict__ dw, const float* __restrict__ db,
                 int H, int W, int lvl_off, float stride, float asize) {
    __shared__ float swt[15 * 256];
    __shared__ float sb[15];
    const int tid = threadIdx.x;
    for (int i = tid; i < 3 * 256; i += 256) swt[i] = objw[i];
    for (int i = tid; i < 12 * 256; i += 256) swt[768 + i] = dw[i];
    if (tid < 3) sb[tid] = objb[tid];
    if (tid >= 3 && tid < 15) sb[tid] = db[tid - 3];
    __syncthreads();

    const int HW = H * W;
    const int pix = blockIdx.x * 256 + tid;
    const int b = blockIdx.y;
    if (pix >= HW) return;

    const float* tb = g_t + (size_t)b * 256 * HW + pix;
    float acc[15];
#pragma unroll
    for (int j = 0; j < 15; j++) acc[j] = sb[j];
    for (int c = 0; c < 256; c++) {
        float tv = tb[(size_t)c * HW];
#pragma unroll
        for (int j = 0; j < 15; j++) acc[j] += tv * swt[j * 256 + c];
    }

    const int py = pix / W, px = pix % W;
    const float cxa = px * stride, cya = py * stride;
    const float ratios[3] = {0.5f, 1.0f, 2.0f};
#pragma unroll
    for (int a = 0; a < 3; a++) {
        float wa = sqrtf(asize * asize / ratios[a]);
        float ha = wa * ratios[a];
        float score = 1.f / (1.f + expf(-acc[a]));
        float dx = acc[3 + a * 4 + 0];
        float dy = acc[3 + a * 4 + 1];
        float dwv = fminf(acc[3 + a * 4 + 2], SCLAMP);
        float dhv = fminf(acc[3 + a * 4 + 3], SCLAMP);
        float cx = dx * wa + cxa;
        float cy = dy * ha + cya;
        float w = expf(dwv) * wa;
        float h = expf(dhv) * ha;
        float x1 = fminf(fmaxf(cx - 0.5f * w, 0.f), 1024.f);
        float y1 = fminf(fmaxf(cy - 0.5f * h, 0.f), 1024.f);
        float x2 = fminf(fmaxf(cx + 0.5f * w, 0.f), 1024.f);
        float y2 = fminf(fmaxf(cy + 0.5f * h, 0.f), 1024.f);
        int gi = lvl_off + pix * 3 + a;
        g_scores[b * NANCH + gi] = score;
        g_boxes[b * NANCH + gi] = make_float4(x1, y1, x2, y2);
    }
}

// ---------------- exact top-1000: 64-bit radix select ----------------
// key = (scoreBits << 32) | ~idx  -> unique keys; descending key order ==
// score desc with index-asc tie-break (matches jax top_k semantics here).
__device__ __forceinline__ unsigned long long make_key(int b, int i) {
    unsigned int sbits = __float_as_uint(g_scores[b * NANCH + i]);
    return ((unsigned long long)sbits << 32) | (unsigned int)(~i);
}

__global__ void hist_kernel(int bp) {
    __shared__ unsigned int sh[256];
    const int b = blockIdx.y;
    for (int i = threadIdx.x; i < 256; i += blockDim.x) sh[i] = 0u;
    __syncthreads();
    const unsigned long long pref = g_pref[b];
    for (int i = blockIdx.x * blockDim.x + threadIdx.x; i < NANCH;
         i += gridDim.x * blockDim.x) {
        unsigned long long key = make_key(b, i);
        bool match = (bp == 7) || (((key ^ pref) >> ((bp + 1) * 8)) == 0ULL);
        if (match) atomicAdd(&sh[(unsigned int)(key >> (bp * 8)) & 255u], 1u);
    }
    __syncthreads();
    for (int i = threadIdx.x; i < 256; i += blockDim.x)
        if (sh[i]) atomicAdd(&g_hist[b][i], sh[i]);
}

__global__ void scan_kernel(int bp) {
    const int b = blockIdx.x;
    if (threadIdx.x == 0) {
        int need = g_need[b];
        int cum = 0, sel = 0;
        for (int v = 255; v >= 0; v--) {
            int h = (int)g_hist[b][v];
            if (cum + h >= need) { sel = v; break; }
            cum += h;
        }
        g_pref[b] |= ((unsigned long long)sel << (bp * 8));
        g_need[b] = need - cum;
    }
    __syncthreads();
    for (int i = threadIdx.x; i < 256; i += blockDim.x) g_hist[b][i] = 0u;
}

__global__ void compact_kernel() {
    const int b = blockIdx.y;
    const unsigned long long thr = g_pref[b];
    for (int i = blockIdx.x * blockDim.x + threadIdx.x; i < NANCH;
         i += gridDim.x * blockDim.x) {
        unsigned long long key = make_key(b, i);
        if (key >= thr) {
            int pos = atomicAdd(&g_cnt[b], 1);
            if (pos < 1024) g_selkey[b][pos] = key;
        }
    }
}

// ---------------- sort 1000 keys desc (bitonic, 1024) + gather boxes ----------------
__global__ __launch_bounds__(1024)
void sort_gather_kernel() {
    __shared__ unsigned long long sk[1024];
    const int b = blockIdx.x, t = threadIdx.x;
    sk[t] = (t < TOPK) ? g_selkey[b][t] : 0ULL;
    __syncthreads();
    for (int k = 2; k <= 1024; k <<= 1) {
        for (int j = k >> 1; j > 0; j >>= 1) {
            int ixj = t ^ j;
            if (ixj > t) {
                bool descSeg = ((t & k) == 0);
                unsigned long long a = sk[t], c = sk[ixj];
                bool doswap = descSeg ? (a < c) : (a > c);
                if (doswap) { sk[t] = c; sk[ixj] = a; }
            }
            __syncthreads();
        }
    }
    if (t < TOPK) {
        unsigned long long key = sk[t];
        unsigned int idx = ~(unsigned int)(key & 0xFFFFFFFFULL);
        g_nbox[b * TOPK + t] = g_boxes[b * NANCH + idx];
    }
}

// ---------------- NMS: suppression mask matrix ----------------
__global__ __launch_bounds__(256)
void nms_mask_kernel() {
    __shared__ float4 sbox[TOPK];
    const int b = blockIdx.y;
    for (int i = threadIdx.x; i < TOPK; i += 256) sbox[i] = g_nbox[b * TOPK + i];
    __syncthreads();
    const int r = blockIdx.x * 8 + (threadIdx.x >> 5);
    const int w = threadIdx.x & 31;
    if (r >= TOPK) return;
    const float4 bi = sbox[r];
    const float areai = (bi.z - bi.x) * (bi.w - bi.y);
    unsigned int bits = 0u;
    const int j0 = w * 32;
#pragma unroll 4
    for (int jj = 0; jj < 32; jj++) {
        int j = j0 + jj;
        if (j < TOPK && j > r) {
            float4 bj = sbox[j];
            float ix1 = fmaxf(bi.x, bj.x), iy1 = fmaxf(bi.y, bj.y);
            float ix2 = fminf(bi.z, bj.z), iy2 = fminf(bi.w, bj.w);
            float inter = fmaxf(ix2 - ix1, 0.f) * fmaxf(iy2 - iy1, 0.f);
            float areaj = (bj.z - bj.x) * (bj.w - bj.y);
            float iou = inter / fmaxf(areai + areaj - inter, 1e-6f);
            if (iou > IOU_T) bits |= (1u << jj);
        }
    }
    g_mask[b][r][w] = bits;
}

// sequential greedy reduce: 1 warp per batch, thread t owns 32-col word t
__global__ void nms_reduce_kernel() {
    const int b = blockIdx.x, t = threadIdx.x;
    unsigned int remv = 0u;
    for (int i = 0; i < TOPK; i++) {
        unsigned int rw = __shfl_sync(0xffffffffu, remv, i >> 5);
        bool removed = (rw >> (i & 31)) & 1u;
        if (!removed) remv |= g_mask[b][i][t];
    }
    g_keep[b][t] = ~remv;
}

// ---------------- output assembly ----------------
// out[0:10000]  = ret (2,1000,5): [0, x1,y1,x2,y2], kept boxes first (score order), rest zero
// out[10000:18000] = dets (2,1000,4)
__global__ __launch_bounds__(1024)
void assemble_kernel(float* __restrict__ out, int out_size) {
    const int b = blockIdx.x, t = threadIdx.x;
    __shared__ unsigned int kw[32];
    __shared__ int wpre[32];
    if (t < 32) {
        unsigned int m = g_keep[b][t];
        if (t == 31) m &= 0xFFu;   // rows 992..999 only
        kw[t] = m;
    }
    __syncthreads();
    if (t == 0) {
        int s = 0;
        for (int i = 0; i < 32; i++) { wpre[i] = s; s += __popc(kw[i]); }
    }
    __syncthreads();
    const bool has_d = (out_size >= 18000);
    for (int i = t; i < 5000; i += 1024) out[b * 5000 + i] = 0.f;
    if (has_d)
        for (int i = t; i < 4000; i += 1024) out[10000 + b * 4000 + i] = 0.f;
    __syncthreads();
    if (t < TOPK) {
        unsigned int w = kw[t >> 5];
        if ((w >> (t & 31)) & 1u) {
            int pos = wpre[t >> 5] + __popc(w & ((1u << (t & 31)) - 1u));
            float4 bx = g_nbox[b * TOPK + t];
            float* r5 = out + (size_t)(b * TOPK + pos) * 5;
            r5[0] = 0.f; r5[1] = bx.x; r5[2] = bx.y; r5[3] = bx.z; r5[4] = bx.w;
            if (has_d) {
                float* r4 = out + 10000 + (size_t)(b * TOPK + pos) * 4;
                r4[0] = bx.x; r4[1] = bx.y; r4[2] = bx.z; r4[3] = bx.w;
            }
        }
    }
}

// ---------------- launch ----------------
extern "C" void kernel_launch(void* const* d_in, const int* in_sizes, int n_in,
                              void* d_out, int out_size) {
    (void)in_sizes; (void)n_in;
    const float* feats[5] = {(const float*)d_in[0], (const float*)d_in[1],
                             (const float*)d_in[2], (const float*)d_in[3],
                             (const float*)d_in[4]};
    const float* conv_w = (const float*)d_in[5];
    const float* conv_b = (const float*)d_in[6];
    const float* obj_w  = (const float*)d_in[7];
    const float* obj_b  = (const float*)d_in[8];
    const float* delta_w = (const float*)d_in[9];
    const float* delta_b = (const float*)d_in[10];
    float* out = (float*)d_out;

    static const int   LH[5]   = {256, 128, 64, 32, 16};
    static const float LSTR[5] = {4.f, 8.f, 16.f, 32.f, 64.f};
    static const float LSZ[5]  = {32.f, 64.f, 128.f, 256.f, 512.f};
    static const int   LOFF[5] = {0, 196608, 245760, 258048, 261120};

    transpose_w_kernel<<<(589824 + 1023) / 1024, 1024>>>(conv_w);
    init_state_kernel<<<1, 256>>>();

    for (int l = 0; l < 5; l++) {
        int H = LH[l], W = LH[l], HW = H * W;
        dim3 gc(W / 8, H / 8, 2);
        conv3x3_kernel<<<gc, 256>>>(feats[l], conv_b, H, W);
        dim3 gh((HW + 255) / 256, 2);
        head_kernel<<<gh, 256>>>(obj_w, obj_b, delta_w, delta_b,
                                 H, W, LOFF[l], LSTR[l], LSZ[l]);
    }

    for (int bp = 7; bp >= 0; bp--) {
        hist_kernel<<<dim3(128, 2), 256>>>(bp);
        scan_kernel<<<2, 256>>>(bp);
    }
    compact_kernel<<<dim3(128, 2), 256>>>();
    sort_gather_kernel<<<2, 1024>>>();
    nms_mask_kernel<<<dim3(125, 2), 256>>>();
    nms_reduce_kernel<<<2, 32>>>();
    assemble_kernel<<<2, 1024>>>(out, out_size);
}

// round 9
// speedup vs baseline: 1.0156x; 1.0156x over previous
#include <cuda_runtime.h>
#include <cuda_fp16.h>
#include <math.h>
#include <stdint.h>

#define NANCH 261888
#define TOPK 1000
#define IOU_T 0.7f
#define SCLAMP 4.1351665567423557f   // log(1000/16)
#define RSCALE 4096.0f
#define RSCALE_INV 0.000244140625f

// ======================= scratch (device globals) =======================
__device__ float g_t[33554432];                   // conv output, NCHW per level
__device__ __half g_Wprep[4 * 2 * 8 * 64 * 288];  // [quarter][hl][chunk][cout64][288]
__device__ float g_wT[589824];                    // transposed weights for fallback conv
__device__ int g_flag;                            // 1 => mma conv mismatch -> fallback
__device__ float g_scores[2 * NANCH];
__device__ float4 g_boxes[2 * NANCH];
__device__ unsigned int g_hist[2][256];
__device__ unsigned long long g_pref[2];
__device__ int g_need[2];
__device__ int g_cnt[2];
__device__ unsigned long long g_selkey[2][1024];
__device__ float4 g_nbox[2 * TOPK];
__device__ unsigned int g_mask[2][TOPK][32];
__device__ unsigned int g_keep[2][32];

// ---------------- f32x2 packed helpers (fallback conv) ----------------
__device__ __forceinline__ void fma2(unsigned long long& acc, unsigned long long a,
                                     unsigned long long b) {
    asm("fma.rn.f32x2 %0, %1, %2, %0;" : "+l"(acc) : "l"(a), "l"(b));
}
__device__ __forceinline__ unsigned long long pack2f(float x, float y) {
    unsigned long long r;
    asm("mov.b64 %0, {%1, %2};" : "=l"(r) : "f"(x), "f"(y));
    return r;
}
__device__ __forceinline__ void unpack2f(float& lo, float& hi, unsigned long long v) {
    asm("mov.b64 {%0, %1}, %2;" : "=f"(lo), "=f"(hi) : "l"(v));
}

// ---------------- mma.sync m16n8k16 fp16 -> fp32 (base ISA, sm_80+) ----------------
#define MMA16816(c, a, b0v, b1v)                                              \
    asm volatile(                                                             \
        "mma.sync.aligned.m16n8k16.row.col.f32.f16.f16.f32 "                  \
        "{%0,%1,%2,%3},{%4,%5,%6,%7},{%8,%9},{%0,%1,%2,%3};"                  \
        : "+f"((c)[0]), "+f"((c)[1]), "+f"((c)[2]), "+f"((c)[3])              \
        : "r"((a)[0]), "r"((a)[1]), "r"((a)[2]), "r"((a)[3]),                 \
          "r"(b0v), "r"(b1v))

// ---------------- weight prep: fp16 hi + scaled-lo split, k-contiguous ----------------
// g_Wprep[q][hl][chunk][cout_l][tap*32+cin_l]; lo scaled by RSCALE (denormal-safe)
__global__ void prep_w_kernel(const float* __restrict__ w) {
    int idx = blockIdx.x * blockDim.x + threadIdx.x;
    if (idx >= 589824) return;                       // 4*8*64*288
    int k = idx % 288;
    int cout_l = (idx / 288) & 63;
    int chunk = (idx / (288 * 64)) & 7;
    int q = idx / (288 * 64 * 8);
    int tap = k / 32, cin_l = k & 31;
    int cout_g = q * 64 + cout_l;
    int cin_g = chunk * 32 + cin_l;
    float v = w[cout_g * 2304 + cin_g * 9 + tap];
    __half h = __float2half_rn(v);
    __half l = __float2half_rn((v - __half2float(h)) * RSCALE);
    size_t baseh = ((size_t)(q * 2 + 0) * 8 + chunk) * 18432 + cout_l * 288 + k;
    size_t basel = ((size_t)(q * 2 + 1) * 8 + chunk) * 18432 + cout_l * 288 + k;
    g_Wprep[baseh] = h;
    g_Wprep[basel] = l;
}
__global__ void transpose_w_kernel(const float* __restrict__ w) {
    int i = blockIdx.x * blockDim.x + threadIdx.x;
    if (i < 589824) {
        int cout = i & 255;
        int rk = i >> 8;            // cin*9+k
        g_wT[i] = w[cout * 2304 + rk];
    }
}

// ---------------- state init (graph replays) ----------------
__global__ void init_state_kernel() {
    int t = threadIdx.x;
    if (t == 0) g_flag = 0;
    if (t < 2) { g_pref[t] = 0ULL; g_need[t] = TOPK; g_cnt[t] = 0; }
    if (t < 256) { g_hist[0][t] = 0u; g_hist[1][t] = 0u; }
}

// ======================= fp16x3 HMMA conv3x3 + bias + relu =======================
// CTA: 16x16 pixel tile (M=256), N=64 couts (blockIdx.z = b*4 + quarter).
// 8 warps, each M32xN64: 2 m16-tiles x 8 n8-tiles, dual accumulators (hh + corr).
#define SM2_BH    0                  // 64*296*2 = 37888
#define SM2_BL    37888
#define SM2_PH    75776              // 18*18*34*2 = 22032
#define SM2_PL    97808
#define SM2_BIAS  119840             // 64 floats
#define SM2_TOTAL 120192

#define BSTRIDE   296                // halfs per cout row (pad 288->296)

__global__ __launch_bounds__(256, 1)
void conv_mma_kernel(const float* __restrict__ x, const float* __restrict__ bias,
                     int H, int W) {
    extern __shared__ char smem[];
    __half* BH = (__half*)(smem + SM2_BH);
    __half* BL = (__half*)(smem + SM2_BL);
    __half* PH = (__half*)(smem + SM2_PH);
    __half* PL = (__half*)(smem + SM2_PL);
    float* sb = (float*)(smem + SM2_BIAS);

    const int tid = threadIdx.x;
    const int lane = tid & 31;
    const int wid = tid >> 5;
    const int wbase = wid * 32;
    const int b = blockIdx.z >> 2;
    const int q = blockIdx.z & 3;
    const int x0 = blockIdx.x * 16, y0 = blockIdx.y * 16;
    const size_t HW = (size_t)H * W;
    const float* xb = x + (size_t)b * 256 * HW;

    if (tid < 64) sb[tid] = bias[q * 64 + tid];

    float acc_hh[2][8][4], acc_cr[2][8][4];
#pragma unroll
    for (int t = 0; t < 2; t++)
#pragma unroll
        for (int nt = 0; nt < 8; nt++)
#pragma unroll
            for (int r = 0; r < 4; r++) { acc_hh[t][nt][r] = 0.f; acc_cr[t][nt][r] = 0.f; }

    for (int chunk = 0; chunk < 8; chunk++) {
        __syncthreads();
        // --- stage B chunk (hi & scaled-lo): 64 rows x 36 uint4 each ---
        {
            const uint4* srcH = (const uint4*)(g_Wprep + ((size_t)(q * 2 + 0) * 8 + chunk) * 18432);
            const uint4* srcL = (const uint4*)(g_Wprep + ((size_t)(q * 2 + 1) * 8 + chunk) * 18432);
            for (int i = tid; i < 2304; i += 256) {
                int row = i / 36, c = i % 36;
                ((uint4*)(BH + row * BSTRIDE))[c] = srcH[i];
                ((uint4*)(BL + row * BSTRIDE))[c] = srcL[i];
            }
        }
        // --- stage patch: 32 cins x 18x18, hi + scaled-lo, cin-contiguous ---
        for (int i = tid; i < 10368; i += 256) {
            int c = i / 324, rem = i % 324, r = rem / 18, col = rem % 18;
            int gy = y0 - 1 + r, gx = x0 - 1 + col;
            float v = 0.f;
            if (gy >= 0 && gy < H && gx >= 0 && gx < W)
                v = xb[(size_t)(chunk * 32 + c) * HW + (size_t)gy * W + gx];
            __half h = __float2half_rn(v);
            int off = (r * 18 + col) * 34 + c;
            PH[off] = h;
            PL[off] = __float2half_rn((v - __half2float(h)) * RSCALE);
        }
        __syncthreads();

        for (int tap = 0; tap < 9; tap++) {
            const int dy = tap / 3, dx = tap % 3;
            int poff[2][2];
#pragma unroll
            for (int t = 0; t < 2; t++)
#pragma unroll
                for (int r = 0; r < 2; r++) {
                    int m = wbase + t * 16 + r * 8 + (lane >> 2);
                    int py = m >> 4, px = m & 15;
                    poff[t][r] = ((py + dy) * 18 + (px + dx)) * 34;
                }
            const int kp = (lane & 3) * 2;
#pragma unroll
            for (int ks = 0; ks < 2; ks++) {
                const int cb = ks * 16;
                uint32_t ah[2][4], al[2][4];
#pragma unroll
                for (int t = 0; t < 2; t++) {
                    ah[t][0] = *(const uint32_t*)(PH + poff[t][0] + cb + kp);
                    ah[t][1] = *(const uint32_t*)(PH + poff[t][1] + cb + kp);
                    ah[t][2] = *(const uint32_t*)(PH + poff[t][0] + cb + kp + 8);
                    ah[t][3] = *(const uint32_t*)(PH + poff[t][1] + cb + kp + 8);
                    al[t][0] = *(const uint32_t*)(PL + poff[t][0] + cb + kp);
                    al[t][1] = *(const uint32_t*)(PL + poff[t][1] + cb + kp);
                    al[t][2] = *(const uint32_t*)(PL + poff[t][0] + cb + kp + 8);
                    al[t][3] = *(const uint32_t*)(PL + poff[t][1] + cb + kp + 8);
                }
                const int bko = tap * 32 + cb + kp;
#pragma unroll
                for (int nt = 0; nt < 8; nt++) {
                    const int n = nt * 8 + (lane >> 2);
                    uint32_t bh0 = *(const uint32_t*)(BH + n * BSTRIDE + bko);
                    uint32_t bh1 = *(const uint32_t*)(BH + n * BSTRIDE + bko + 8);
                    uint32_t bl0 = *(const uint32_t*)(BL + n * BSTRIDE + bko);
                    uint32_t bl1 = *(const uint32_t*)(BL + n * BSTRIDE + bko + 8);
#pragma unroll
                    for (int t = 0; t < 2; t++) {
                        MMA16816(acc_hh[t][nt], ah[t], bh0, bh1);
                        MMA16816(acc_cr[t][nt], ah[t], bl0, bl1);
                        MMA16816(acc_cr[t][nt], al[t], bh0, bh1);
                    }
                }
            }
        }
    }
    __syncthreads();

    // ---- epilogue: hh + corr/RSCALE + bias, relu -> g_t ----
#pragma unroll
    for (int t = 0; t < 2; t++) {
        const int m0 = wbase + t * 16 + (lane >> 2);
        const int m1 = m0 + 8;
        const size_t p0 = (size_t)(y0 + (m0 >> 4)) * W + (x0 + (m0 & 15));
        const size_t p1 = (size_t)(y0 + (m1 >> 4)) * W + (x0 + (m1 & 15));
#pragma unroll
        for (int nt = 0; nt < 8; nt++) {
            const int n = nt * 8 + (lane & 3) * 2;
            const int cg0 = q * 64 + n;
            float v0 = acc_hh[t][nt][0] + acc_cr[t][nt][0] * RSCALE_INV + sb[n];
            float v1 = acc_hh[t][nt][1] + acc_cr[t][nt][1] * RSCALE_INV + sb[n + 1];
            float v2 = acc_hh[t][nt][2] + acc_cr[t][nt][2] * RSCALE_INV + sb[n];
            float v3 = acc_hh[t][nt][3] + acc_cr[t][nt][3] * RSCALE_INV + sb[n + 1];
            g_t[((size_t)(b * 256 + cg0)) * HW + p0]     = v0 > 0.f ? v0 : 0.f;
            g_t[((size_t)(b * 256 + cg0 + 1)) * HW + p0] = v1 > 0.f ? v1 : 0.f;
            g_t[((size_t)(b * 256 + cg0)) * HW + p1]     = v2 > 0.f ? v2 : 0.f;
            g_t[((size_t)(b * 256 + cg0 + 1)) * HW + p1] = v3 > 0.f ? v3 : 0.f;
        }
    }
}

// ---------------- verify: hashed samples, tight threshold ----------------
__global__ void verify_kernel(const float* __restrict__ x,
                              const float* __restrict__ w,
                              const float* __restrict__ bias,
                              int H, int W) {
    const int t = blockIdx.x * blockDim.x + threadIdx.x;   // 1024 samples
    const uint32_t p = (uint32_t)t * 2654435761u;
    const int b = t & 1;
    const int cout = (p >> 4) & 255;
    const int y = (int)((p >> 12) & 1023) % H;
    const int xg = (int)((p >> 22)) % W;
    const size_t HW = (size_t)H * W;
    const float* xb = x + (size_t)b * 256 * HW;
    float acc = bias[cout];
    for (int c = 0; c < 256; c++) {
        const float* wr = w + cout * 2304 + c * 9;
        for (int k = 0; k < 9; k++) {
            int gy = y - 1 + k / 3, gx = xg - 1 + k % 3;
            if (gy >= 0 && gy < H && gx >= 0 && gx < W)
                acc += xb[(size_t)c * HW + (size_t)gy * W + gx] * wr[k];
        }
    }
    float ref = acc > 0.f ? acc : 0.f;
    float got = g_t[((size_t)(b * 256 + cout)) * HW + (size_t)y * W + xg];
    float err = fabsf(got - ref) / fmaxf(fabsf(ref), 1.0f);
    if (err > 5e-5f) atomicExch(&g_flag, 1);
}

// ---------------- fallback conv (fp32 f32x2; predicated on g_flag) ----------------
__global__ __launch_bounds__(256, 2)
void conv_fb_kernel(const float* __restrict__ x, const float* __restrict__ bias,
                    int H, int W) {
    __shared__ int sflag;
    if (threadIdx.x == 0) sflag = *((volatile int*)&g_flag);
    __syncthreads();
    if (!sflag) return;

    const int tx0 = blockIdx.x * 8, ty0 = blockIdx.y * 8, b = blockIdx.z;
    const int tid = threadIdx.x;
    const int coutq = tid & 31;
    const int prow = tid >> 5;
    __shared__ float sx[4][10][10];
    __shared__ __align__(16) float sw[4 * 9 * 256];
    unsigned long long acc2[4][8];
#pragma unroll
    for (int p = 0; p < 4; p++)
#pragma unroll
        for (int j = 0; j < 8; j++) acc2[p][j] = 0ULL;

    const size_t HW = (size_t)H * W;
    const float* xb = x + (size_t)b * 256 * HW;

    for (int c0 = 0; c0 < 256; c0 += 4) {
        __syncthreads();
        for (int i = tid; i < 400; i += 256) {
            int ci = i / 100, p = i % 100, py = p / 10, px = p % 10;
            int gy = ty0 - 1 + py, gx = tx0 - 1 + px;
            float v = 0.f;
            if (gy >= 0 && gy < H && gx >= 0 && gx < W)
                v = xb[(size_t)(c0 + ci) * HW + (size_t)gy * W + gx];
            sx[ci][py][px] = v;
        }
        const float* wsrc = g_wT + (size_t)c0 * 9 * 256;
        for (int i = tid; i < 9216; i += 256) sw[i] = wsrc[i];
        __syncthreads();

#pragma unroll
        for (int ci = 0; ci < 4; ci++) {
            float xr[3][10];
#pragma unroll
            for (int r = 0; r < 3; r++)
#pragma unroll
                for (int j = 0; j < 10; j++) xr[r][j] = sx[ci][prow + r][j];
#pragma unroll
            for (int k = 0; k < 9; k++) {
                const int ky = k / 3, kx = k % 3;
                const ulonglong2* wrow = (const ulonglong2*)(sw + (ci * 9 + k) * 256);
                ulonglong2 wA = wrow[coutq * 2];
                ulonglong2 wB = wrow[coutq * 2 + 1];
#pragma unroll
                for (int px = 0; px < 8; px++) {
                    float xv = xr[ky][px + kx];
                    unsigned long long xv2 = pack2f(xv, xv);
                    fma2(acc2[0][px], xv2, wA.x);
                    fma2(acc2[1][px], xv2, wA.y);
                    fma2(acc2[2][px], xv2, wB.x);
                    fma2(acc2[3][px], xv2, wB.y);
                }
            }
        }
    }
    const size_t ob = (size_t)b * 256 * HW;
    const int y = ty0 + prow;
#pragma unroll
    for (int p = 0; p < 4; p++) {
        int cout0 = coutq * 8 + 2 * p;
        float bv0 = bias[cout0], bv1 = bias[cout0 + 1];
        float o0[8], o1[8];
#pragma unroll
        for (int px = 0; px < 8; px++) {
            float lo, hi;
            unpack2f(lo, hi, acc2[p][px]);
            lo += bv0; hi += bv1;
            o0[px] = lo > 0.f ? lo : 0.f;
            o1[px] = hi > 0.f ? hi : 0.f;
        }
        float4* d0 = (float4*)(g_t + ob + (size_t)cout0 * HW + (size_t)y * W + tx0);
        d0[0] = make_float4(o0[0], o0[1], o0[2], o0[3]);
        d0[1] = make_float4(o0[4], o0[5], o0[6], o0[7]);
        float4* d1 = (float4*)(g_t + ob + (size_t)(cout0 + 1) * HW + (size_t)y * W + tx0);
        d1[0] = make_float4(o1[0], o1[1], o1[2], o1[3]);
        d1[1] = make_float4(o1[4], o1[5], o1[6], o1[7]);
    }
}

// ---------------- 1x1 heads + sigmoid + decode + clip ----------------
__global__ __launch_bounds__(256)
void head_kernel(const float* __restrict__ objw, const float* __restrict__ objb,
                 const float* __restrict__ dw, const float* __restrict__ db,
                 int H, int W, int lvl_off, float stride, float asize) {
    __shared__ float swt[15 * 256];
    __shared__ float sb[15];
    const int tid = threadIdx.x;
    for (int i = tid; i < 3 * 256; i += 256) swt[i] = objw[i];
    for (int i = tid; i < 12 * 256; i += 256) swt[768 + i] = dw[i];
    if (tid < 3) sb[tid] = objb[tid];
    if (tid >= 3 && tid < 15) sb[tid] = db[tid - 3];
    __syncthreads();

    const int HW = H * W;
    const int pix = blockIdx.x * 256 + tid;
    const int b = blockIdx.y;
    if (pix >= HW) return;

    const float* tb = g_t + (size_t)b * 256 * HW + pix;
    float acc[15];
#pragma unroll
    for (int j = 0; j < 15; j++) acc[j] = sb[j];
    for (int c = 0; c < 256; c++) {
        float tv = tb[(size_t)c * HW];
#pragma unroll
        for (int j = 0; j < 15; j++) acc[j] += tv * swt[j * 256 + c];
    }

    const int py = pix / W, px = pix % W;
    const float cxa = px * stride, cya = py * stride;
    const float ratios[3] = {0.5f, 1.0f, 2.0f};
#pragma unroll
    for (int a = 0; a < 3; a++) {
        float wa = sqrtf(asize * asize / ratios[a]);
        float ha = wa * ratios[a];
        float score = 1.f / (1.f + expf(-acc[a]));
        float dxv = acc[3 + a * 4 + 0];
        float dyv = acc[3 + a * 4 + 1];
        float dwv = fminf(acc[3 + a * 4 + 2], SCLAMP);
        float dhv = fminf(acc[3 + a * 4 + 3], SCLAMP);
        float cx = dxv * wa + cxa;
        float cy = dyv * ha + cya;
        float w = expf(dwv) * wa;
        float h = expf(dhv) * ha;
        float x1 = fminf(fmaxf(cx - 0.5f * w, 0.f), 1024.f);
        float y1 = fminf(fmaxf(cy - 0.5f * h, 0.f), 1024.f);
        float x2 = fminf(fmaxf(cx + 0.5f * w, 0.f), 1024.f);
        float y2 = fminf(fmaxf(cy + 0.5f * h, 0.f), 1024.f);
        int gi = lvl_off + pix * 3 + a;
        g_scores[b * NANCH + gi] = score;
        g_boxes[b * NANCH + gi] = make_float4(x1, y1, x2, y2);
    }
}

// ---------------- exact top-1000: 64-bit radix select ----------------
__device__ __forceinline__ unsigned long long make_key(int b, int i) {
    unsigned int sbits = __float_as_uint(g_scores[b * NANCH + i]);
    return ((unsigned long long)sbits << 32) | (unsigned int)(~i);
}

__global__ void hist_kernel(int bp) {
    __shared__ unsigned int sh[256];
    const int b = blockIdx.y;
    for (int i = threadIdx.x; i < 256; i += blockDim.x) sh[i] = 0u;
    __syncthreads();
    const unsigned long long pref = g_pref[b];
    for (int i = blockIdx.x * blockDim.x + threadIdx.x; i < NANCH;
         i += gridDim.x * blockDim.x) {
        unsigned long long key = make_key(b, i);
        bool match = (bp == 7) || (((key ^ pref) >> ((bp + 1) * 8)) == 0ULL);
        if (match) atomicAdd(&sh[(unsigned int)(key >> (bp * 8)) & 255u], 1u);
    }
    __syncthreads();
    for (int i = threadIdx.x; i < 256; i += blockDim.x)
        if (sh[i]) atomicAdd(&g_hist[b][i], sh[i]);
}

__global__ void scan_kernel(int bp) {
    const int b = blockIdx.x;
    if (threadIdx.x == 0) {
        int need = g_need[b];
        int cum = 0, sel = 0;
        for (int v = 255; v >= 0; v--) {
            int h = (int)g_hist[b][v];
            if (cum + h >= need) { sel = v; break; }
            cum += h;
        }
        g_pref[b] |= ((unsigned long long)sel << (bp * 8));
        g_need[b] = need - cum;
    }
    __syncthreads();
    for (int i = threadIdx.x; i < 256; i += blockDim.x) g_hist[b][i] = 0u;
}

__global__ void compact_kernel() {
    const int b = blockIdx.y;
    const unsigned long long thr = g_pref[b];
    for (int i = blockIdx.x * blockDim.x + threadIdx.x; i < NANCH;
         i += gridDim.x * blockDim.x) {
        unsigned long long key = make_key(b, i);
        if (key >= thr) {
            int pos = atomicAdd(&g_cnt[b], 1);
            if (pos < 1024) g_selkey[b][pos] = key;
        }
    }
}

// ---------------- sort 1000 keys desc (bitonic 1024) + gather ----------------
__global__ __launch_bounds__(1024)
void sort_gather_kernel() {
    __shared__ unsigned long long sk[1024];
    const int b = blockIdx.x, t = threadIdx.x;
    sk[t] = (t < TOPK) ? g_selkey[b][t] : 0ULL;
    __syncthreads();
    for (int k = 2; k <= 1024; k <<= 1) {
        for (int j = k >> 1; j > 0; j >>= 1) {
            int ixj = t ^ j;
            if (ixj > t) {
                bool descSeg = ((t & k) == 0);
                unsigned long long a = sk[t], c = sk[ixj];
                bool doswap = descSeg ? (a < c) : (a > c);
                if (doswap) { sk[t] = c; sk[ixj] = a; }
            }
            __syncthreads();
        }
    }
    if (t < TOPK) {
        unsigned long long key = sk[t];
        unsigned int idx = ~(unsigned int)(key & 0xFFFFFFFFULL);
        g_nbox[b * TOPK + t] = g_boxes[b * NANCH + idx];
    }
}

// ---------------- NMS mask + reduce ----------------
__global__ __launch_bounds__(256)
void nms_mask_kernel() {
    __shared__ float4 sbox[TOPK];
    const int b = blockIdx.y;
    for (int i = threadIdx.x; i < TOPK; i += 256) sbox[i] = g_nbox[b * TOPK + i];
    __syncthreads();
    const int r = blockIdx.x * 8 + (threadIdx.x >> 5);
    const int w = threadIdx.x & 31;
    if (r >= TOPK) return;
    const float4 bi = sbox[r];
    const float areai = (bi.z - bi.x) * (bi.w - bi.y);
    unsigned int bits = 0u;
    const int j0 = w * 32;
#pragma unroll 4
    for (int jj = 0; jj < 32; jj++) {
        int j = j0 + jj;
        if (j < TOPK && j > r) {
            float4 bj = sbox[j];
            float ix1 = fmaxf(bi.x, bj.x), iy1 = fmaxf(bi.y, bj.y);
            float ix2 = fminf(bi.z, bj.z), iy2 = fminf(bi.w, bj.w);
            float inter = fmaxf(ix2 - ix1, 0.f) * fmaxf(iy2 - iy1, 0.f);
            float areaj = (bj.z - bj.x) * (bj.w - bj.y);
            float iou = inter / fmaxf(areai + areaj - inter, 1e-6f);
            if (iou > IOU_T) bits |= (1u << jj);
        }
    }
    g_mask[b][r][w] = bits;
}

__global__ void nms_reduce_kernel() {
    const int b = blockIdx.x, t = threadIdx.x;
    unsigned int remv = 0u;
    for (int i = 0; i < TOPK; i++) {
        unsigned int rw = __shfl_sync(0xffffffffu, remv, i >> 5);
        bool removed = (rw >> (i & 31)) & 1u;
        if (!removed) remv |= g_mask[b][i][t];
    }
    g_keep[b][t] = ~remv;
}

// ---------------- output assembly ----------------
__global__ __launch_bounds__(1024)
void assemble_kernel(float* __restrict__ out, int out_size) {
    const int b = blockIdx.x, t = threadIdx.x;
    __shared__ unsigned int kw[32];
    __shared__ int wpre[32];
    if (t < 32) {
        unsigned int m = g_keep[b][t];
        if (t == 31) m &= 0xFFu;
        kw[t] = m;
    }
    __syncthreads();
    if (t == 0) {
        int s = 0;
        for (int i = 0; i < 32; i++) { wpre[i] = s; s += __popc(kw[i]); }
    }
    __syncthreads();
    const bool has_d = (out_size >= 18000);
    for (int i = t; i < 5000; i += 1024) out[b * 5000 + i] = 0.f;
    if (has_d)
        for (int i = t; i < 4000; i += 1024) out[10000 + b * 4000 + i] = 0.f;
    __syncthreads();
    if (t < TOPK) {
        unsigned int w = kw[t >> 5];
        if ((w >> (t & 31)) & 1u) {
            int pos = wpre[t >> 5] + __popc(w & ((1u << (t & 31)) - 1u));
            float4 bx = g_nbox[b * TOPK + t];
            float* r5 = out + (size_t)(b * TOPK + pos) * 5;
            r5[0] = 0.f; r5[1] = bx.x; r5[2] = bx.y; r5[3] = bx.z; r5[4] = bx.w;
            if (has_d) {
                float* r4 = out + 10000 + (size_t)(b * TOPK + pos) * 4;
                r4[0] = bx.x; r4[1] = bx.y; r4[2] = bx.z; r4[3] = bx.w;
            }
        }
    }
}

// ---------------- launch ----------------
extern "C" void kernel_launch(void* const* d_in, const int* in_sizes, int n_in,
                              void* d_out, int out_size) {
    (void)in_sizes; (void)n_in;
    const float* feats[5] = {(const float*)d_in[0], (const float*)d_in[1],
                             (const float*)d_in[2], (const float*)d_in[3],
                             (const float*)d_in[4]};
    const float* conv_w = (const float*)d_in[5];
    const float* conv_b = (const float*)d_in[6];
    const float* obj_w  = (const float*)d_in[7];
    const float* obj_b  = (const float*)d_in[8];
    const float* delta_w = (const float*)d_in[9];
    const float* delta_b = (const float*)d_in[10];
    float* out = (float*)d_out;

    static const int   LH[5]   = {256, 128, 64, 32, 16};
    static const float LSTR[5] = {4.f, 8.f, 16.f, 32.f, 64.f};
    static const float LSZ[5]  = {32.f, 64.f, 128.f, 256.f, 512.f};
    static const int   LOFF[5] = {0, 196608, 245760, 258048, 261120};

    cudaFuncSetAttribute(conv_mma_kernel,
                         cudaFuncAttributeMaxDynamicSharedMemorySize, SM2_TOTAL);

    prep_w_kernel<<<(589824 + 255) / 256, 256>>>(conv_w);
    transpose_w_kernel<<<(589824 + 1023) / 1024, 1024>>>(conv_w);
    init_state_kernel<<<1, 256>>>();

    for (int l = 0; l < 5; l++) {
        int H = LH[l], W = LH[l], HW = H * W;
        dim3 gc(W / 16, H / 16, 8);              // z = b*4 + quarter
        conv_mma_kernel<<<gc, 256, SM2_TOTAL>>>(feats[l], conv_b, H, W);
        verify_kernel<<<4, 256>>>(feats[l], conv_w, conv_b, H, W);
        dim3 gf(W / 8, H / 8, 2);
        conv_fb_kernel<<<gf, 256>>>(feats[l], conv_b, H, W);
        dim3 gh((HW + 255) / 256, 2);
        head_kernel<<<gh, 256>>>(obj_w, obj_b, delta_w, delta_b,
                                 H, W, LOFF[l], LSTR[l], LSZ[l]);
    }

    for (int bp = 7; bp >= 0; bp--) {
        hist_kernel<<<dim3(128, 2), 256>>>(bp);
        scan_kernel<<<2, 256>>>(bp);
    }
    compact_kernel<<<dim3(128, 2), 256>>>();
    sort_gather_kernel<<<2, 1024>>>();
    nms_mask_kernel<<<dim3(125, 2), 256>>>();
    nms_reduce_kernel<<<2, 32>>>();
    assemble_kernel<<<2, 1024>>>(out, out_size);
}

// round 11
// speedup vs baseline: 1.0257x; 1.0099x over previous
#include <cuda_runtime.h>
#include <cuda_fp16.h>
#include <math.h>
#include <stdint.h>

#define NANCH 261888
#define TOPK 1000
#define IOU_T 0.7f
#define SCLAMP 4.1351665567423557f   // log(1000/16)
#define RSCALE 4096.0f
#define RSCALE_INV 0.000244140625f

// ======================= scratch (device globals) =======================
__device__ float g_t[33554432];                   // conv output, NCHW per level
__device__ __half g_Wprep[4 * 2 * 8 * 64 * 288];  // [quarter][hl][chunk][cout64][288] (k-permuted)
__device__ float g_wT[589824];                    // transposed weights for fallback conv
__device__ int g_flag;                            // 1 => mma conv mismatch -> fallback
__device__ float g_scores[2 * NANCH];
__device__ float4 g_boxes[2 * NANCH];
__device__ unsigned int g_hist[2][256];
__device__ unsigned long long g_pref[2];
__device__ int g_need[2];
__device__ int g_cnt[2];
__device__ unsigned long long g_selkey[2][1024];
__device__ float4 g_nbox[2 * TOPK];
__device__ unsigned int g_mask[2][TOPK][32];
__device__ unsigned int g_keep[2][32];

// k-permutation within a 16-group: thread kp=(lane&3)*2 reads {kp,kp+1,kp+8,kp+9}
// stored contiguously at 2*kp -> single LDS.64 per fragment pair.
__device__ __host__ __forceinline__ int kperm16(int k) {
    return 4 * ((k & 7) >> 1) + 2 * (k >> 3) + (k & 1);
}

// ---------------- f32x2 packed helpers (fallback conv) ----------------
__device__ __forceinline__ void fma2(unsigned long long& acc, unsigned long long a,
                                     unsigned long long b) {
    asm("fma.rn.f32x2 %0, %1, %2, %0;" : "+l"(acc) : "l"(a), "l"(b));
}
__device__ __forceinline__ unsigned long long pack2f(float x, float y) {
    unsigned long long r;
    asm("mov.b64 %0, {%1, %2};" : "=l"(r) : "f"(x), "f"(y));
    return r;
}
__device__ __forceinline__ void unpack2f(float& lo, float& hi, unsigned long long v) {
    asm("mov.b64 {%0, %1}, %2;" : "=f"(lo), "=f"(hi) : "l"(v));
}

// ---------------- mma.sync m16n8k16 fp16 -> fp32 (base ISA) ----------------
#define MMA16816(c, a0, a1, a2, a3, b0v, b1v)                                 \
    asm volatile(                                                             \
        "mma.sync.aligned.m16n8k16.row.col.f32.f16.f16.f32 "                  \
        "{%0,%1,%2,%3},{%4,%5,%6,%7},{%8,%9},{%0,%1,%2,%3};"                  \
        : "+f"((c)[0]), "+f"((c)[1]), "+f"((c)[2]), "+f"((c)[3])              \
        : "r"(a0), "r"(a1), "r"(a2), "r"(a3),                                 \
          "r"(b0v), "r"(b1v))

// ---------------- weight prep: fp16 hi + scaled-lo, k-permuted tiles ----------------
__global__ void prep_w_kernel(const float* __restrict__ w) {
    int idx = blockIdx.x * blockDim.x + threadIdx.x;
    if (idx >= 589824) return;                       // 4*8*64*288
    int k = idx % 288;
    int cout_l = (idx / 288) & 63;
    int chunk = (idx / (288 * 64)) & 7;
    int q = idx / (288 * 64 * 8);
    int tap = k / 32, cin_l = k & 31;
    int cout_g = q * 64 + cout_l;
    int cin_g = chunk * 32 + cin_l;
    float v = w[cout_g * 2304 + cin_g * 9 + tap];
    __half h = __float2half_rn(v);
    __half l = __float2half_rn((v - __half2float(h)) * RSCALE);
    int kp = tap * 32 + (cin_l & 16) + kperm16(cin_l & 15);
    size_t baseh = ((size_t)(q * 2 + 0) * 8 + chunk) * 18432 + cout_l * 288 + kp;
    size_t basel = ((size_t)(q * 2 + 1) * 8 + chunk) * 18432 + cout_l * 288 + kp;
    g_Wprep[baseh] = h;
    g_Wprep[basel] = l;
}
__global__ void transpose_w_kernel(const float* __restrict__ w) {
    int i = blockIdx.x * blockDim.x + threadIdx.x;
    if (i < 589824) {
        int cout = i & 255;
        int rk = i >> 8;            // cin*9+k
        g_wT[i] = w[cout * 2304 + rk];
    }
}

// ---------------- state init (graph replays) ----------------
__global__ void init_state_kernel() {
    int t = threadIdx.x;
    if (t == 0) g_flag = 0;
    if (t < 2) { g_pref[t] = 0ULL; g_need[t] = TOPK; g_cnt[t] = 0; }
    if (t < 256) { g_hist[0][t] = 0u; g_hist[1][t] = 0u; }
}

// ======================= fp16x3 HMMA conv3x3 + bias + relu (v2) =======================
// CTA: 512 threads / 16 warps. M=256 pixels (16x16 tile), N=64 couts (z = b*4+q).
// Warp w: m16 tile = pixels [w*16, w*16+16), 8 n8-tiles. Dual acc (hh + scaled corr).
#define SM2_BH    0                  // 64*296*2 = 37888
#define SM2_BL    37888
#define SM2_PH    75776              // 324*36*2 = 23328
#define SM2_PL    99104
#define SM2_BIAS  122432             // 64 floats
#define SM2_TOTAL 122880

#define BSTRIDE   296                // halfs per cout row (288 pad to 296)
#define PSTRIDE   36                 // halfs per spatial pos (32 cins pad to 36; 72B, 8B-aligned)

__global__ __launch_bounds__(512, 1)
void conv_mma_kernel(const float* __restrict__ x, const float* __restrict__ bias,
                     int H, int W) {
    extern __shared__ char smem[];
    __half* BH = (__half*)(smem + SM2_BH);
    __half* BL = (__half*)(smem + SM2_BL);
    __half* PH = (__half*)(smem + SM2_PH);
    __half* PL = (__half*)(smem + SM2_PL);
    float* sb = (float*)(smem + SM2_BIAS);

    const int tid = threadIdx.x;
    const int lane = tid & 31;
    const int wid = tid >> 5;
    const int b = blockIdx.z >> 2;
    const int q = blockIdx.z & 3;
    const int x0 = blockIdx.x * 16, y0 = blockIdx.y * 16;
    const size_t HW = (size_t)H * W;
    const float* xb = x + (size_t)b * 256 * HW;

    if (tid < 64) sb[tid] = bias[q * 64 + tid];

    float acc_hh[8][4], acc_cr[8][4];
#pragma unroll
    for (int nt = 0; nt < 8; nt++)
#pragma unroll
        for (int r = 0; r < 4; r++) { acc_hh[nt][r] = 0.f; acc_cr[nt][r] = 0.f; }

    const int kp2 = (lane & 3) * 4;          // 2*kp in halfs
    const int nrow = lane >> 2;              // 0..7

    for (int chunk = 0; chunk < 8; chunk++) {
        __syncthreads();
        // --- stage B chunk (hi & scaled-lo): 64 rows x 36 uint4 each ---
        {
            const uint4* srcH = (const uint4*)(g_Wprep + ((size_t)(q * 2 + 0) * 8 + chunk) * 18432);
            const uint4* srcL = (const uint4*)(g_Wprep + ((size_t)(q * 2 + 1) * 8 + chunk) * 18432);
            for (int i = tid; i < 2304; i += 512) {
                int row = i / 36, c = i % 36;
                ((uint4*)(BH + row * BSTRIDE))[c] = srcH[i];
                ((uint4*)(BL + row * BSTRIDE))[c] = srcL[i];
            }
        }
        // --- stage patch: 32 cins x 18x18, hi + scaled-lo, k-permuted cin ---
        for (int i = tid; i < 10368; i += 512) {
            int c = i / 324, rem = i % 324, r = rem / 18, col = rem % 18;
            int gy = y0 - 1 + r, gx = x0 - 1 + col;
            float v = 0.f;
            if (gy >= 0 && gy < H && gx >= 0 && gx < W)
                v = xb[(size_t)(chunk * 32 + c) * HW + (size_t)gy * W + gx];
            __half h = __float2half_rn(v);
            int cp = (c & 16) + kperm16(c & 15);
            int off = (r * 18 + col) * PSTRIDE + cp;
            PH[off] = h;
            PL[off] = __float2half_rn((v - __half2float(h)) * RSCALE);
        }
        __syncthreads();

        for (int tap = 0; tap < 9; tap++) {
            const int dy = tap / 3, dx = tap % 3;
            // warp's two pixel rows for this m16 tile
            const int m0 = wid * 16 + nrow;
            const int m1 = m0 + 8;
            const int poff0 = (((m0 >> 4) + dy) * 18 + (m0 & 15) + dx) * PSTRIDE;
            const int poff1 = (((m1 >> 4) + dy) * 18 + (m1 & 15) + dx) * PSTRIDE;
#pragma unroll
            for (int ks = 0; ks < 2; ks++) {
                const int cb = ks * 16;
                // A fragments: 4x LDS.64 (hi row0/row1, lo row0/row1)
                uint2 a0h = *(const uint2*)(PH + poff0 + cb + kp2);
                uint2 a1h = *(const uint2*)(PH + poff1 + cb + kp2);
                uint2 a0l = *(const uint2*)(PL + poff0 + cb + kp2);
                uint2 a1l = *(const uint2*)(PL + poff1 + cb + kp2);
                const int bko = tap * 32 + cb + kp2;
                // loop A: hh += aH*bH ; cr += aL*bH (no same-acc back-to-back)
#pragma unroll
                for (int nt = 0; nt < 8; nt++) {
                    uint2 bh = *(const uint2*)(BH + (nt * 8 + nrow) * BSTRIDE + bko);
                    MMA16816(acc_hh[nt], a0h.x, a1h.x, a0h.y, a1h.y, bh.x, bh.y);
                    MMA16816(acc_cr[nt], a0l.x, a1l.x, a0l.y, a1l.y, bh.x, bh.y);
                }
                // loop B: cr += aH*bL
#pragma unroll
                for (int nt = 0; nt < 8; nt++) {
                    uint2 bl = *(const uint2*)(BL + (nt * 8 + nrow) * BSTRIDE + bko);
                    MMA16816(acc_cr[nt], a0h.x, a1h.x, a0h.y, a1h.y, bl.x, bl.y);
                }
            }
        }
    }
    __syncthreads();

    // ---- epilogue: hh + corr/RSCALE + bias, relu -> g_t ----
    {
        const int m0 = wid * 16 + nrow;
        const int m1 = m0 + 8;
        const size_t p0 = (size_t)(y0 + (m0 >> 4)) * W + (x0 + (m0 & 15));
        const size_t p1 = (size_t)(y0 + (m1 >> 4)) * W + (x0 + (m1 & 15));
#pragma unroll
        for (int nt = 0; nt < 8; nt++) {
            const int n = nt * 8 + (lane & 3) * 2;
            const int cg0 = q * 64 + n;
            float v0 = acc_hh[nt][0] + acc_cr[nt][0] * RSCALE_INV + sb[n];
            float v1 = acc_hh[nt][1] + acc_cr[nt][1] * RSCALE_INV + sb[n + 1];
            float v2 = acc_hh[nt][2] + acc_cr[nt][2] * RSCALE_INV + sb[n];
            float v3 = acc_hh[nt][3] + acc_cr[nt][3] * RSCALE_INV + sb[n + 1];
            g_t[((size_t)(b * 256 + cg0)) * HW + p0]     = v0 > 0.f ? v0 : 0.f;
            g_t[((size_t)(b * 256 + cg0 + 1)) * HW + p0] = v1 > 0.f ? v1 : 0.f;
            g_t[((size_t)(b * 256 + cg0)) * HW + p1]     = v2 > 0.f ? v2 : 0.f;
            g_t[((size_t)(b * 256 + cg0 + 1)) * HW + p1] = v3 > 0.f ? v3 : 0.f;
        }
    }
}

// ---------------- verify: hashed samples, tight threshold ----------------
__global__ void verify_kernel(const float* __restrict__ x,
                              const float* __restrict__ w,
                              const float* __restrict__ bias,
                              int H, int W) {
    const int t = blockIdx.x * blockDim.x + threadIdx.x;   // 1024 samples
    const uint32_t p = (uint32_t)t * 2654435761u;
    const int b = t & 1;
    const int cout = (p >> 4) & 255;
    const int y = (int)((p >> 12) & 1023) % H;
    const int xg = (int)((p >> 22)) % W;
    const size_t HW = (size_t)H * W;
    const float* xb = x + (size_t)b * 256 * HW;
    float acc = bias[cout];
    for (int c = 0; c < 256; c++) {
        const float* wr = w + cout * 2304 + c * 9;
        for (int k = 0; k < 9; k++) {
            int gy = y - 1 + k / 3, gx = xg - 1 + k % 3;
            if (gy >= 0 && gy < H && gx >= 0 && gx < W)
                acc += xb[(size_t)c * HW + (size_t)gy * W + gx] * wr[k];
        }
    }
    float ref = acc > 0.f ? acc : 0.f;
    float got = g_t[((size_t)(b * 256 + cout)) * HW + (size_t)y * W + xg];
    float err = fabsf(got - ref) / fmaxf(fabsf(ref), 1.0f);
    if (err > 5e-5f) atomicExch(&g_flag, 1);
}

// ---------------- fallback conv (fp32 f32x2; predicated on g_flag) ----------------
__global__ __launch_bounds__(256, 2)
void conv_fb_kernel(const float* __restrict__ x, const float* __restrict__ bias,
                    int H, int W) {
    __shared__ int sflag;
    if (threadIdx.x == 0) sflag = *((volatile int*)&g_flag);
    __syncthreads();
    if (!sflag) return;

    const int tx0 = blockIdx.x * 8, ty0 = blockIdx.y * 8, b = blockIdx.z;
    const int tid = threadIdx.x;
    const int coutq = tid & 31;
    const int prow = tid >> 5;
    __shared__ float sx[4][10][10];
    __shared__ __align__(16) float sw[4 * 9 * 256];
    unsigned long long acc2[4][8];
#pragma unroll
    for (int p = 0; p < 4; p++)
#pragma unroll
        for (int j = 0; j < 8; j++) acc2[p][j] = 0ULL;

    const size_t HW = (size_t)H * W;
    const float* xb = x + (size_t)b * 256 * HW;

    for (int c0 = 0; c0 < 256; c0 += 4) {
        __syncthreads();
        for (int i = tid; i < 400; i += 256) {
            int ci = i / 100, p = i % 100, py = p / 10, px = p % 10;
            int gy = ty0 - 1 + py, gx = tx0 - 1 + px;
            float v = 0.f;
            if (gy >= 0 && gy < H && gx >= 0 && gx < W)
                v = xb[(size_t)(c0 + ci) * HW + (size_t)gy * W + gx];
            sx[ci][py][px] = v;
        }
        const float* wsrc = g_wT + (size_t)c0 * 9 * 256;
        for (int i = tid; i < 9216; i += 256) sw[i] = wsrc[i];
        __syncthreads();

#pragma unroll
        for (int ci = 0; ci < 4; ci++) {
            float xr[3][10];
#pragma unroll
            for (int r = 0; r < 3; r++)
#pragma unroll
                for (int j = 0; j < 10; j++) xr[r][j] = sx[ci][prow + r][j];
#pragma unroll
            for (int k = 0; k < 9; k++) {
                const int ky = k / 3, kx = k % 3;
                const ulonglong2* wrow = (const ulonglong2*)(sw + (ci * 9 + k) * 256);
                ulonglong2 wA = wrow[coutq * 2];
                ulonglong2 wB = wrow[coutq * 2 + 1];
#pragma unroll
                for (int px = 0; px < 8; px++) {
                    float xv = xr[ky][px + kx];
                    unsigned long long xv2 = pack2f(xv, xv);
                    fma2(acc2[0][px], xv2, wA.x);
                    fma2(acc2[1][px], xv2, wA.y);
                    fma2(acc2[2][px], xv2, wB.x);
                    fma2(acc2[3][px], xv2, wB.y);
                }
            }
        }
    }
    const size_t ob = (size_t)b * 256 * HW;
    const int y = ty0 + prow;
#pragma unroll
    for (int p = 0; p < 4; p++) {
        int cout0 = coutq * 8 + 2 * p;
        float bv0 = bias[cout0], bv1 = bias[cout0 + 1];
        float o0[8], o1[8];
#pragma unroll
        for (int px = 0; px < 8; px++) {
            float lo, hi;
            unpack2f(lo, hi, acc2[p][px]);
            lo += bv0; hi += bv1;
            o0[px] = lo > 0.f ? lo : 0.f;
            o1[px] = hi > 0.f ? hi : 0.f;
        }
        float4* d0 = (float4*)(g_t + ob + (size_t)cout0 * HW + (size_t)y * W + tx0);
        d0[0] = make_float4(o0[0], o0[1], o0[2], o0[3]);
        d0[1] = make_float4(o0[4], o0[5], o0[6], o0[7]);
        float4* d1 = (float4*)(g_t + ob + (size_t)(cout0 + 1) * HW + (size_t)y * W + tx0);
        d1[0] = make_float4(o1[0], o1[1], o1[2], o1[3]);
        d1[1] = make_float4(o1[4], o1[5], o1[6], o1[7]);
    }
}

// ---------------- 1x1 heads + sigmoid + decode + clip ----------------
__global__ __launch_bounds__(256)
void head_kernel(const float* __restrict__ objw, const float* __restrict__ objb,
                 const float* __restrict__ dw, const float* __restrict__ db,
                 int H, int W, int lvl_off, float stride, float asize) {
    __shared__ float swt[15 * 256];
    __shared__ float sb[15];
    const int tid = threadIdx.x;
    for (int i = tid; i < 3 * 256; i += 256) swt[i] = objw[i];
    for (int i = tid; i < 12 * 256; i += 256) swt[768 + i] = dw[i];
    if (tid < 3) sb[tid] = objb[tid];
    if (tid >= 3 && tid < 15) sb[tid] = db[tid - 3];
    __syncthreads();

    const int HW = H * W;
    const int pix = blockIdx.x * 256 + tid;
    const int b = blockIdx.y;
    if (pix >= HW) return;

    const float* tb = g_t + (size_t)b * 256 * HW + pix;
    float acc[15];
#pragma unroll
    for (int j = 0; j < 15; j++) acc[j] = sb[j];
    for (int c = 0; c < 256; c++) {
        float tv = tb[(size_t)c * HW];
#pragma unroll
        for (int j = 0; j < 15; j++) acc[j] += tv * swt[j * 256 + c];
    }

    const int py = pix / W, px = pix % W;
    const float cxa = px * stride, cya = py * stride;
    const float ratios[3] = {0.5f, 1.0f, 2.0f};
#pragma unroll
    for (int a = 0; a < 3; a++) {
        float wa = sqrtf(asize * asize / ratios[a]);
        float ha = wa * ratios[a];
        float score = 1.f / (1.f + expf(-acc[a]));
        float dxv = acc[3 + a * 4 + 0];
        float dyv = acc[3 + a * 4 + 1];
        float dwv = fminf(acc[3 + a * 4 + 2], SCLAMP);
        float dhv = fminf(acc[3 + a * 4 + 3], SCLAMP);
        float cx = dxv * wa + cxa;
        float cy = dyv * ha + cya;
        float w = expf(dwv) * wa;
        float h = expf(dhv) * ha;
        float x1 = fminf(fmaxf(cx - 0.5f * w, 0.f), 1024.f);
        float y1 = fminf(fmaxf(cy - 0.5f * h, 0.f), 1024.f);
        float x2 = fminf(fmaxf(cx + 0.5f * w, 0.f), 1024.f);
        float y2 = fminf(fmaxf(cy + 0.5f * h, 0.f), 1024.f);
        int gi = lvl_off + pix * 3 + a;
        g_scores[b * NANCH + gi] = score;
        g_boxes[b * NANCH + gi] = make_float4(x1, y1, x2, y2);
    }
}

// ---------------- exact top-1000: 64-bit radix select ----------------
__device__ __forceinline__ unsigned long long make_key(int b, int i) {
    unsigned int sbits = __float_as_uint(g_scores[b * NANCH + i]);
    return ((unsigned long long)sbits << 32) | (unsigned int)(~i);
}

__global__ void hist_kernel(int bp) {
    __shared__ unsigned int sh[256];
    const int b = blockIdx.y;
    for (int i = threadIdx.x; i < 256; i += blockDim.x) sh[i] = 0u;
    __syncthreads();
    const unsigned long long pref = g_pref[b];
    for (int i = blockIdx.x * blockDim.x + threadIdx.x; i < NANCH;
         i += gridDim.x * blockDim.x) {
        unsigned long long key = make_key(b, i);
        bool match = (bp == 7) || (((key ^ pref) >> ((bp + 1) * 8)) == 0ULL);
        if (match) atomicAdd(&sh[(unsigned int)(key >> (bp * 8)) & 255u], 1u);
    }
    __syncthreads();
    for (int i = threadIdx.x; i < 256; i += blockDim.x)
        if (sh[i]) atomicAdd(&g_hist[b][i], sh[i]);
}

__global__ void scan_kernel(int bp) {
    const int b = blockIdx.x;
    if (threadIdx.x == 0) {
        int need = g_need[b];
        int cum = 0, sel = 0;
        for (int v = 255; v >= 0; v--) {
            int h = (int)g_hist[b][v];
            if (cum + h >= need) { sel = v; break; }
            cum += h;
        }
        g_pref[b] |= ((unsigned long long)sel << (bp * 8));
        g_need[b] = need - cum;
    }
    __syncthreads();
    for (int i = threadIdx.x; i < 256; i += blockDim.x) g_hist[b][i] = 0u;
}

__global__ void compact_kernel() {
    const int b = blockIdx.y;
    const unsigned long long thr = g_pref[b];
    for (int i = blockIdx.x * blockDim.x + threadIdx.x; i < NANCH;
         i += gridDim.x * blockDim.x) {
        unsigned long long key = make_key(b, i);
        if (key >= thr) {
            int pos = atomicAdd(&g_cnt[b], 1);
            if (pos < 1024) g_selkey[b][pos] = key;
        }
    }
}

// ---------------- sort 1000 keys desc (bitonic 1024) + gather ----------------
__global__ __launch_bounds__(1024)
void sort_gather_kernel() {
    __shared__ unsigned long long sk[1024];
    const int b = blockIdx.x, t = threadIdx.x;
    sk[t] = (t < TOPK) ? g_selkey[b][t] : 0ULL;
    __syncthreads();
    for (int k = 2; k <= 1024; k <<= 1) {
        for (int j = k >> 1; j > 0; j >>= 1) {
            int ixj = t ^ j;
            if (ixj > t) {
                bool descSeg = ((t & k) == 0);
                unsigned long long a = sk[t], c = sk[ixj];
                bool doswap = descSeg ? (a < c) : (a > c);
                if (doswap) { sk[t] = c; sk[ixj] = a; }
            }
            __syncthreads();
        }
    }
    if (t < TOPK) {
        unsigned long long key = sk[t];
        unsigned int idx = ~(unsigned int)(key & 0xFFFFFFFFULL);
        g_nbox[b * TOPK + t] = g_boxes[b * NANCH + idx];
    }
}

// ---------------- NMS mask + reduce ----------------
__global__ __launch_bounds__(256)
void nms_mask_kernel() {
    __shared__ float4 sbox[TOPK];
    const int b = blockIdx.y;
    for (int i = threadIdx.x; i < TOPK; i += 256) sbox[i] = g_nbox[b * TOPK + i];
    __syncthreads();
    const int r = blockIdx.x * 8 + (threadIdx.x >> 5);
    const int w = threadIdx.x & 31;
    if (r >= TOPK) return;
    const float4 bi = sbox[r];
    const float areai = (bi.z - bi.x) * (bi.w - bi.y);
    unsigned int bits = 0u;
    const int j0 = w * 32;
#pragma unroll 4
    for (int jj = 0; jj < 32; jj++) {
        int j = j0 + jj;
        if (j < TOPK && j > r) {
            float4 bj = sbox[j];
            float ix1 = fmaxf(bi.x, bj.x), iy1 = fmaxf(bi.y, bj.y);
            float ix2 = fminf(bi.z, bj.z), iy2 = fminf(bi.w, bj.w);
            float inter = fmaxf(ix2 - ix1, 0.f) * fmaxf(iy2 - iy1, 0.f);
            float areaj = (bj.z - bj.x) * (bj.w - bj.y);
            float iou = inter / fmaxf(areai + areaj - inter, 1e-6f);
            if (iou > IOU_T) bits |= (1u << jj);
        }
    }
    g_mask[b][r][w] = bits;
}

__global__ void nms_reduce_kernel() {
    const int b = blockIdx.x, t = threadIdx.x;
    unsigned int remv = 0u;
    for (int i = 0; i < TOPK; i++) {
        unsigned int rw = __shfl_sync(0xffffffffu, remv, i >> 5);
        bool removed = (rw >> (i & 31)) & 1u;
        if (!removed) remv |= g_mask[b][i][t];
    }
    g_keep[b][t] = ~remv;
}

// ---------------- output assembly ----------------
__global__ __launch_bounds__(1024)
void assemble_kernel(float* __restrict__ out, int out_size) {
    const int b = blockIdx.x, t = threadIdx.x;
    __shared__ unsigned int kw[32];
    __shared__ int wpre[32];
    if (t < 32) {
        unsigned int m = g_keep[b][t];
        if (t == 31) m &= 0xFFu;
        kw[t] = m;
    }
    __syncthreads();
    if (t == 0) {
        int s = 0;
        for (int i = 0; i < 32; i++) { wpre[i] = s; s += __popc(kw[i]); }
    }
    __syncthreads();
    const bool has_d = (out_size >= 18000);
    for (int i = t; i < 5000; i += 1024) out[b * 5000 + i] = 0.f;
    if (has_d)
        for (int i = t; i < 4000; i += 1024) out[10000 + b * 4000 + i] = 0.f;
    __syncthreads();
    if (t < TOPK) {
        unsigned int w = kw[t >> 5];
        if ((w >> (t & 31)) & 1u) {
            int pos = wpre[t >> 5] + __popc(w & ((1u << (t & 31)) - 1u));
            float4 bx = g_nbox[b * TOPK + t];
            float* r5 = out + (size_t)(b * TOPK + pos) * 5;
            r5[0] = 0.f; r5[1] = bx.x; r5[2] = bx.y; r5[3] = bx.z; r5[4] = bx.w;
            if (has_d) {
                float* r4 = out + 10000 + (size_t)(b * TOPK + pos) * 4;
                r4[0] = bx.x; r4[1] = bx.y; r4[2] = bx.z; r4[3] = bx.w;
            }
        }
    }
}

// ---------------- launch ----------------
extern "C" void kernel_launch(void* const* d_in, const int* in_sizes, int n_in,
                              void* d_out, int out_size) {
    (void)in_sizes; (void)n_in;
    const float* feats[5] = {(const float*)d_in[0], (const float*)d_in[1],
                             (const float*)d_in[2], (const float*)d_in[3],
                             (const float*)d_in[4]};
    const float* conv_w = (const float*)d_in[5];
    const float* conv_b = (const float*)d_in[6];
    const float* obj_w  = (const float*)d_in[7];
    const float* obj_b  = (const float*)d_in[8];
    const float* delta_w = (const float*)d_in[9];
    const float* delta_b = (const float*)d_in[10];
    float* out = (float*)d_out;

    static const int   LH[5]   = {256, 128, 64, 32, 16};
    static const float LSTR[5] = {4.f, 8.f, 16.f, 32.f, 64.f};
    static const float LSZ[5]  = {32.f, 64.f, 128.f, 256.f, 512.f};
    static const int   LOFF[5] = {0, 196608, 245760, 258048, 261120};

    cudaFuncSetAttribute(conv_mma_kernel,
                         cudaFuncAttributeMaxDynamicSharedMemorySize, SM2_TOTAL);

    prep_w_kernel<<<(589824 + 255) / 256, 256>>>(conv_w);
    transpose_w_kernel<<<(589824 + 1023) / 1024, 1024>>>(conv_w);
    init_state_kernel<<<1, 256>>>();

    for (int l = 0; l < 5; l++) {
        int H = LH[l], W = LH[l], HW = H * W;
        dim3 gc(W / 16, H / 16, 8);              // z = b*4 + quarter
        conv_mma_kernel<<<gc, 512, SM2_TOTAL>>>(feats[l], conv_b, H, W);
        verify_kernel<<<4, 256>>>(feats[l], conv_w, conv_b, H, W);
        dim3 gf(W / 8, H / 8, 2);
        conv_fb_kernel<<<gf, 256>>>(feats[l], conv_b, H, W);
        dim3 gh((HW + 255) / 256, 2);
        head_kernel<<<gh, 256>>>(obj_w, obj_b, delta_w, delta_b,
                                 H, W, LOFF[l], LSTR[l], LSZ[l]);
    }

    for (int bp = 7; bp >= 0; bp--) {
        hist_kernel<<<dim3(128, 2), 256>>>(bp);
        scan_kernel<<<2, 256>>>(bp);
    }
    compact_kernel<<<dim3(128, 2), 256>>>();
    sort_gather_kernel<<<2, 1024>>>();
    nms_mask_kernel<<<dim3(125, 2), 256>>>();
    nms_reduce_kernel<<<2, 32>>>();
    assemble_kernel<<<2, 1024>>>(out, out_size);
}